// round 14
// baseline (speedup 1.0000x reference)
#include <cuda_runtime.h>
#include <stdint.h>

#define BB 8
#define LL 4096
#define KK 576
#define DD 4096
#define IMG_TOK 32000
#define IGNORE (-100.0f)

#define NCOPY (BB * LL)                    // 32768 copy blocks, 1 row each
#define CHUNK 1024                         // tokens per scan block
#define NSCANB (BB * LL / CHUNK)           // 32 scan blocks (launched FIRST)

// ---------------------------------------------------------------------------
// One kernel, all blocks fully independent (no inter-block sync, no state).
//  bid < NSCANB : one 1024-token chunk of the small outputs (wave 1 -> hidden)
//  bid >= NSCANB: stream ONE embedding row. Image-token prefix count runs
//                 with trip-count 0 for text rows (branchless gating).
//                 Bulk input reads use evict-first (.cs): zero reuse.
// ---------------------------------------------------------------------------
__global__ __launch_bounds__(256) void fused_kernel(
    const int*    __restrict__ input_ids,
    const int*    __restrict__ attention_mask,
    const int*    __restrict__ labels,
    const float4* __restrict__ feat,       // (B,K,D)
    const float4* __restrict__ emb,        // (B,L,D)
    float4*       __restrict__ out,        // (B,L,D)
    float*        __restrict__ out_tail)   // out + B*L*D
{
    const int bid  = blockIdx.x;
    const int tid  = threadIdx.x;          // 0..255
    const int lane = tid & 31;
    const int wid  = tid >> 5;             // 8 warps

    if (bid >= NSCANB) {
        // ================= COPY PATH (1 row, 256 threads) =================
        const int row = bid - NSCANB;            // 0 .. B*L-1
        const int b   = row >> 12;               // batch row
        const int l0  = row & (LL - 1);          // position within the row
        const int* ids_row = input_ids + b * LL;

        const int my_id = ids_row[l0];           // uniform broadcast load
        // trip count is 0 for text rows -> loop vanishes, no branch structure
        const int need = (my_id == IMG_TOK) ? l0 : 0;

        int local = 0;
        for (int i0 = tid * 4; i0 < need; i0 += 1024) {
            int4 v = *(const int4*)(ids_row + i0);      // aligned, in-bounds
            local += (v.x == IMG_TOK && i0 + 0 < need)
                   + (v.y == IMG_TOK && i0 + 1 < need)
                   + (v.z == IMG_TOK && i0 + 2 < need)
                   + (v.w == IMG_TOK && i0 + 3 < need);
        }
        #pragma unroll
        for (int o = 16; o; o >>= 1) local += __shfl_down_sync(~0u, local, o);

        __shared__ int s_warp[8];
        if (lane == 0) s_warp[wid] = local;
        __syncthreads();
        int rank = s_warp[0] + s_warp[1] + s_warp[2] + s_warp[3]
                 + s_warp[4] + s_warp[5] + s_warp[6] + s_warp[7];

        const int D4 = DD / 4;                   // 1024 float4 per row
        float4* dst = out + (size_t)row * D4;

        if (my_id == IMG_TOK && rank >= KK) {
            // extra placeholder -> zeros
            float4 z = make_float4(0.f, 0.f, 0.f, 0.f);
            #pragma unroll
            for (int i = 0; i < 4; i++) dst[i * 256 + tid] = z;
        } else {
            const float4* src = (my_id == IMG_TOK)
                ? feat + ((size_t)b * KK + rank) * D4
                : emb  + (size_t)row * D4;
            float4 r0 = __ldcs(src + 0 * 256 + tid);   // evict-first reads
            float4 r1 = __ldcs(src + 1 * 256 + tid);
            float4 r2 = __ldcs(src + 2 * 256 + tid);
            float4 r3 = __ldcs(src + 3 * 256 + tid);
            dst[0 * 256 + tid] = r0;                   // write-back stores
            dst[1 * 256 + tid] = r1;
            dst[2 * 256 + tid] = r2;
            dst[3 * 256 + tid] = r3;
        }
    } else {
        // ================= SCAN PATH (one 1024-token chunk) ===============
        const int sb    = bid;                    // 0..31
        const int b     = sb >> 2;                // batch row
        const int chunk = sb & 3;                 // which quarter of the row
        const int cs    = chunk * CHUNK;          // chunk start (local)
        const int* ids_row = input_ids + b * LL;
        const int* am_row  = attention_mask + b * LL;

        // ---- redundant prefix over [0, cs): img count + non-img attn sum --
        int img_pre = 0, amn_pre = 0;
        for (int k = 0; k < chunk; k++) {
            int i = (k * 256 + tid) * 4;
            int4 v = *(const int4*)(ids_row + i);
            int4 a = *(const int4*)(am_row + i);
            img_pre += (v.x == IMG_TOK) + (v.y == IMG_TOK)
                     + (v.z == IMG_TOK) + (v.w == IMG_TOK);
            amn_pre += (v.x == IMG_TOK ? 0 : a.x) + (v.y == IMG_TOK ? 0 : a.y)
                     + (v.z == IMG_TOK ? 0 : a.z) + (v.w == IMG_TOK ? 0 : a.w);
        }
        #pragma unroll
        for (int o = 16; o; o >>= 1) {
            img_pre += __shfl_down_sync(~0u, img_pre, o);
            amn_pre += __shfl_down_sync(~0u, amn_pre, o);
        }
        __shared__ int s_img, s_amn;
        if (tid == 0) { s_img = 0; s_amn = 0; }
        __syncthreads();
        if (lane == 0) {
            if (img_pre) atomicAdd(&s_img, img_pre);
            if (amn_pre) atomicAdd(&s_amn, amn_pre);
        }
        __syncthreads();
        const int IMG_PRE  = s_img;
        // attn prefix: writes before cs = min(img_pre, K); plus text attn sum
        const int ATTN_PRE = (IMG_PRE < KK ? IMG_PRE : KK) + s_amn;

        // ---- chunk body: 256 threads x 4 tokens ----
        const int base = b * LL + cs + tid * 4;   // global token index
        int4 id4 = *(const int4*)(input_ids + base);
        int im[4] = { id4.x == IMG_TOK, id4.y == IMG_TOK,
                      id4.z == IMG_TOK, id4.w == IMG_TOK };
        int local = im[0] + im[1] + im[2] + im[3];

        __shared__ int warp_sums[8];

        // block scan #1: in-chunk image-token ranks
        int v = local;
        #pragma unroll
        for (int o = 1; o < 32; o <<= 1) { int n = __shfl_up_sync(~0u, v, o); if (lane >= o) v += n; }
        if (lane == 31) warp_sums[wid] = v;
        __syncthreads();
        if (wid == 0 && lane < 8) {
            int s = warp_sums[lane];
            #pragma unroll
            for (int o = 1; o < 8; o <<= 1) {
                int n = __shfl_up_sync(0xffu, s, o); if (lane >= o) s += n;
            }
            warp_sums[lane] = s;
        }
        __syncthreads();
        int rank0 = IMG_PRE + (v - local) + (wid > 0 ? warp_sums[wid - 1] : 0);

        int4 am4 = *(const int4*)(attention_mask + base);
        int4 lb4 = *(const int4*)(labels + base);
        int am[4] = { am4.x, am4.y, am4.z, am4.w };
        int lb[4] = { lb4.x, lb4.y, lb4.z, lb4.w };

        int   fattn[4];
        float flab[4], fmask[4];
        int run = rank0;
        #pragma unroll
        for (int i = 0; i < 4; i++) {
            if (im[i]) {
                int wr = (run < KK); run++;
                fattn[i] = wr;
                fmask[i] = wr ? 1.0f : 0.0f;     // extra -> id PAD(0)
                flab[i]  = IGNORE;
            } else {
                fattn[i] = am[i];
                fmask[i] = 0.0f;
                flab[i]  = (float)lb[i];
            }
        }

        __syncthreads();   // reuse warp_sums
        // block scan #2: in-chunk attn cumsum -> position_ids
        int local2 = fattn[0] + fattn[1] + fattn[2] + fattn[3];
        int v2 = local2;
        #pragma unroll
        for (int o = 1; o < 32; o <<= 1) { int n = __shfl_up_sync(~0u, v2, o); if (lane >= o) v2 += n; }
        if (lane == 31) warp_sums[wid] = v2;
        __syncthreads();
        if (wid == 0 && lane < 8) {
            int s = warp_sums[lane];
            #pragma unroll
            for (int o = 1; o < 8; o <<= 1) {
                int n = __shfl_up_sync(0xffu, s, o); if (lane >= o) s += n;
            }
            warp_sums[lane] = s;
        }
        __syncthreads();
        int csum = ATTN_PRE + (v2 - local2) + (wid > 0 ? warp_sums[wid - 1] : 0);

        float fpos[4];
        #pragma unroll
        for (int i = 0; i < 4; i++) {
            csum += fattn[i];
            int p = csum - 1;
            fpos[i] = (float)(p < 0 ? 0 : p);
        }

        const int NTOK = BB * LL;
        *(float4*)(out_tail + 0 * NTOK + base) =
            make_float4((float)fattn[0], (float)fattn[1], (float)fattn[2], (float)fattn[3]);
        *(float4*)(out_tail + 1 * NTOK + base) = make_float4(flab[0], flab[1], flab[2], flab[3]);
        *(float4*)(out_tail + 2 * NTOK + base) = make_float4(fpos[0], fpos[1], fpos[2], fpos[3]);
        *(float4*)(out_tail + 3 * NTOK + base) = make_float4(fmask[0], fmask[1], fmask[2], fmask[3]);
    }
}

// ---------------------------------------------------------------------------
extern "C" void kernel_launch(void* const* d_in, const int* in_sizes, int n_in,
                              void* d_out, int out_size)
{
    const float* image_features = (const float*)d_in[0];   // (B,K,D) f32
    const float* inputs_embeds  = (const float*)d_in[1];   // (B,L,D) f32
    const int*   input_ids      = (const int*)d_in[2];     // (B,L) i32
    const int*   attention_mask = (const int*)d_in[3];     // (B,L) i32
    const int*   labels         = (const int*)d_in[4];     // (B,L) i32

    float* out = (float*)d_out;
    float* out_tail = out + (size_t)BB * LL * DD;

    fused_kernel<<<NSCANB + NCOPY, 256>>>(
        input_ids, attention_mask, labels,
        (const float4*)image_features,
        (const float4*)inputs_embeds,
        (float4*)out, out_tail);
}

// round 15
// speedup vs baseline: 1.0114x; 1.0114x over previous
#include <cuda_runtime.h>
#include <stdint.h>

#define BB 8
#define LL 4096
#define KK 576
#define DD 4096
#define IMG_TOK 32000
#define IGNORE (-100.0f)

#define NCOPY (BB * LL)                    // 32768 copy blocks, 1 row each
#define CHUNK 1024                         // tokens per scan block
#define NSCANB (BB * LL / CHUNK)           // 32 scan blocks (launched FIRST)

// ---------------------------------------------------------------------------
// One kernel, all blocks fully independent (no inter-block sync, no state).
//  bid < NSCANB : one 1024-token chunk of the small outputs (wave 1 -> hidden)
//  bid >= NSCANB: stream ONE embedding row. Image-token prefix count runs
//                 with trip-count 0 for text rows (branchless gating).
// ---------------------------------------------------------------------------
__global__ __launch_bounds__(256) void fused_kernel(
    const int*    __restrict__ input_ids,
    const int*    __restrict__ attention_mask,
    const int*    __restrict__ labels,
    const float4* __restrict__ feat,       // (B,K,D)
    const float4* __restrict__ emb,        // (B,L,D)
    float4*       __restrict__ out,        // (B,L,D)
    float*        __restrict__ out_tail)   // out + B*L*D
{
    const int bid  = blockIdx.x;
    const int tid  = threadIdx.x;          // 0..255
    const int lane = tid & 31;
    const int wid  = tid >> 5;             // 8 warps

    if (bid >= NSCANB) {
        // ================= COPY PATH (1 row, 256 threads) =================
        const int row = bid - NSCANB;            // 0 .. B*L-1
        const int b   = row >> 12;               // batch row
        const int l0  = row & (LL - 1);          // position within the row
        const int* ids_row = input_ids + b * LL;

        const int my_id = ids_row[l0];           // uniform broadcast load
        // trip count is 0 for text rows -> loop vanishes, no branch structure
        const int need = (my_id == IMG_TOK) ? l0 : 0;

        int local = 0;
        for (int i0 = tid * 4; i0 < need; i0 += 1024) {
            int4 v = *(const int4*)(ids_row + i0);      // aligned, in-bounds
            local += (v.x == IMG_TOK && i0 + 0 < need)
                   + (v.y == IMG_TOK && i0 + 1 < need)
                   + (v.z == IMG_TOK && i0 + 2 < need)
                   + (v.w == IMG_TOK && i0 + 3 < need);
        }
        #pragma unroll
        for (int o = 16; o; o >>= 1) local += __shfl_down_sync(~0u, local, o);

        __shared__ int s_warp[8];
        if (lane == 0) s_warp[wid] = local;
        __syncthreads();
        int rank = s_warp[0] + s_warp[1] + s_warp[2] + s_warp[3]
                 + s_warp[4] + s_warp[5] + s_warp[6] + s_warp[7];

        const int D4 = DD / 4;                   // 1024 float4 per row
        float4* dst = out + (size_t)row * D4;

        if (my_id == IMG_TOK && rank >= KK) {
            // extra placeholder -> zeros
            float4 z = make_float4(0.f, 0.f, 0.f, 0.f);
            #pragma unroll
            for (int i = 0; i < 4; i++) dst[i * 256 + tid] = z;
        } else {
            const float4* src = (my_id == IMG_TOK)
                ? feat + ((size_t)b * KK + rank) * D4
                : emb  + (size_t)row * D4;
            float4 r0 = src[0 * 256 + tid];
            float4 r1 = src[1 * 256 + tid];
            float4 r2 = src[2 * 256 + tid];
            float4 r3 = src[3 * 256 + tid];
            dst[0 * 256 + tid] = r0;
            dst[1 * 256 + tid] = r1;
            dst[2 * 256 + tid] = r2;
            dst[3 * 256 + tid] = r3;
        }
    } else {
        // ================= SCAN PATH (one 1024-token chunk) ===============
        const int sb    = bid;                    // 0..31
        const int b     = sb >> 2;                // batch row
        const int chunk = sb & 3;                 // which quarter of the row
        const int cs    = chunk * CHUNK;          // chunk start (local)
        const int* ids_row = input_ids + b * LL;
        const int* am_row  = attention_mask + b * LL;

        // ---- redundant prefix over [0, cs): img count + non-img attn sum --
        int img_pre = 0, amn_pre = 0;
        for (int k = 0; k < chunk; k++) {
            int i = (k * 256 + tid) * 4;
            int4 v = *(const int4*)(ids_row + i);
            int4 a = *(const int4*)(am_row + i);
            img_pre += (v.x == IMG_TOK) + (v.y == IMG_TOK)
                     + (v.z == IMG_TOK) + (v.w == IMG_TOK);
            amn_pre += (v.x == IMG_TOK ? 0 : a.x) + (v.y == IMG_TOK ? 0 : a.y)
                     + (v.z == IMG_TOK ? 0 : a.z) + (v.w == IMG_TOK ? 0 : a.w);
        }
        #pragma unroll
        for (int o = 16; o; o >>= 1) {
            img_pre += __shfl_down_sync(~0u, img_pre, o);
            amn_pre += __shfl_down_sync(~0u, amn_pre, o);
        }
        __shared__ int s_img, s_amn;
        if (tid == 0) { s_img = 0; s_amn = 0; }
        __syncthreads();
        if (lane == 0) {
            if (img_pre) atomicAdd(&s_img, img_pre);
            if (amn_pre) atomicAdd(&s_amn, amn_pre);
        }
        __syncthreads();
        const int IMG_PRE  = s_img;
        // attn prefix: writes before cs = min(img_pre, K); plus text attn sum
        const int ATTN_PRE = (IMG_PRE < KK ? IMG_PRE : KK) + s_amn;

        // ---- chunk body: 256 threads x 4 tokens ----
        const int base = b * LL + cs + tid * 4;   // global token index
        int4 id4 = *(const int4*)(input_ids + base);
        int im[4] = { id4.x == IMG_TOK, id4.y == IMG_TOK,
                      id4.z == IMG_TOK, id4.w == IMG_TOK };
        int local = im[0] + im[1] + im[2] + im[3];

        __shared__ int warp_sums[8];

        // block scan #1: in-chunk image-token ranks
        int v = local;
        #pragma unroll
        for (int o = 1; o < 32; o <<= 1) { int n = __shfl_up_sync(~0u, v, o); if (lane >= o) v += n; }
        if (lane == 31) warp_sums[wid] = v;
        __syncthreads();
        if (wid == 0 && lane < 8) {
            int s = warp_sums[lane];
            #pragma unroll
            for (int o = 1; o < 8; o <<= 1) {
                int n = __shfl_up_sync(0xffu, s, o); if (lane >= o) s += n;
            }
            warp_sums[lane] = s;
        }
        __syncthreads();
        int rank0 = IMG_PRE + (v - local) + (wid > 0 ? warp_sums[wid - 1] : 0);

        int4 am4 = *(const int4*)(attention_mask + base);
        int4 lb4 = *(const int4*)(labels + base);
        int am[4] = { am4.x, am4.y, am4.z, am4.w };
        int lb[4] = { lb4.x, lb4.y, lb4.z, lb4.w };

        int   fattn[4];
        float flab[4], fmask[4];
        int run = rank0;
        #pragma unroll
        for (int i = 0; i < 4; i++) {
            if (im[i]) {
                int wr = (run < KK); run++;
                fattn[i] = wr;
                fmask[i] = wr ? 1.0f : 0.0f;     // extra -> id PAD(0)
                flab[i]  = IGNORE;
            } else {
                fattn[i] = am[i];
                fmask[i] = 0.0f;
                flab[i]  = (float)lb[i];
            }
        }

        __syncthreads();   // reuse warp_sums
        // block scan #2: in-chunk attn cumsum -> position_ids
        int local2 = fattn[0] + fattn[1] + fattn[2] + fattn[3];
        int v2 = local2;
        #pragma unroll
        for (int o = 1; o < 32; o <<= 1) { int n = __shfl_up_sync(~0u, v2, o); if (lane >= o) v2 += n; }
        if (lane == 31) warp_sums[wid] = v2;
        __syncthreads();
        if (wid == 0 && lane < 8) {
            int s = warp_sums[lane];
            #pragma unroll
            for (int o = 1; o < 8; o <<= 1) {
                int n = __shfl_up_sync(0xffu, s, o); if (lane >= o) s += n;
            }
            warp_sums[lane] = s;
        }
        __syncthreads();
        int csum = ATTN_PRE + (v2 - local2) + (wid > 0 ? warp_sums[wid - 1] : 0);

        float fpos[4];
        #pragma unroll
        for (int i = 0; i < 4; i++) {
            csum += fattn[i];
            int p = csum - 1;
            fpos[i] = (float)(p < 0 ? 0 : p);
        }

        const int NTOK = BB * LL;
        *(float4*)(out_tail + 0 * NTOK + base) =
            make_float4((float)fattn[0], (float)fattn[1], (float)fattn[2], (float)fattn[3]);
        *(float4*)(out_tail + 1 * NTOK + base) = make_float4(flab[0], flab[1], flab[2], flab[3]);
        *(float4*)(out_tail + 2 * NTOK + base) = make_float4(fpos[0], fpos[1], fpos[2], fpos[3]);
        *(float4*)(out_tail + 3 * NTOK + base) = make_float4(fmask[0], fmask[1], fmask[2], fmask[3]);
    }
}

// ---------------------------------------------------------------------------
extern "C" void kernel_launch(void* const* d_in, const int* in_sizes, int n_in,
                              void* d_out, int out_size)
{
    const float* image_features = (const float*)d_in[0];   // (B,K,D) f32
    const float* inputs_embeds  = (const float*)d_in[1];   // (B,L,D) f32
    const int*   input_ids      = (const int*)d_in[2];     // (B,L) i32
    const int*   attention_mask = (const int*)d_in[3];     // (B,L) i32
    const int*   labels         = (const int*)d_in[4];     // (B,L) i32

    float* out = (float*)d_out;
    float* out_tail = out + (size_t)BB * LL * DD;

    fused_kernel<<<NSCANB + NCOPY, 256>>>(
        input_ids, attention_mask, labels,
        (const float4*)image_features,
        (const float4*)inputs_embeds,
        (float4*)out, out_tail);
}